// round 16
// baseline (speedup 1.0000x reference)
#include <cuda_runtime.h>
#include <cuda_fp16.h>
#include <math.h>
#include <stdint.h>

// ---------------- problem constants ----------------
namespace cfg {
constexpr int B = 2, T = 2048, D = 1024, H = 16, HD = 64, F = 4096, V = 32000;
constexpr int M = B * T;
constexpr int D3 = 3 * D;
constexpr float EPS = 1e-6f;
}

// ---------------- scratch ----------------------------------------------------
__device__ float g_h[cfg::M * cfg::D];
__device__ float g_o[cfg::M * cfg::D];

__device__ __half g_x16[(size_t)cfg::M * cfg::F];
__device__ __half g_h16[cfg::M * cfg::D];
__device__ __half g_o16[cfg::M * cfg::D];
__device__ __half g_qkv[(size_t)cfg::M * cfg::D3];

__device__ __half g_wqkv[(size_t)cfg::D * cfg::D3];
__device__ float  g_bqkv[cfg::D3];

// ---------------- PTX helpers -------------------------------------------------
__device__ __forceinline__ uint32_t smem_u32(const void* p) {
    uint32_t a;
    asm("{ .reg .u64 t; cvta.to.shared.u64 t, %1; cvt.u32.u64 %0, t; }" : "=r"(a) : "l"(p));
    return a;
}
__device__ __forceinline__ void cp16(uint32_t dst, const void* src) {
    asm volatile("cp.async.cg.shared.global [%0], [%1], 16;" :: "r"(dst), "l"(src));
}
__device__ __forceinline__ void cp_commit() {
    asm volatile("cp.async.commit_group;" ::: "memory");
}
template <int N>
__device__ __forceinline__ void cp_wait() {
    asm volatile("cp.async.wait_group %0;" :: "n"(N) : "memory");
}
__device__ __forceinline__ void ldmat4(uint32_t* r, uint32_t addr) {
    asm volatile("ldmatrix.sync.aligned.m8n8.x4.shared.b16 {%0,%1,%2,%3}, [%4];"
                 : "=r"(r[0]), "=r"(r[1]), "=r"(r[2]), "=r"(r[3]) : "r"(addr));
}
__device__ __forceinline__ void ldmat4t(uint32_t* r, uint32_t addr) {
    asm volatile("ldmatrix.sync.aligned.m8n8.x4.trans.shared.b16 {%0,%1,%2,%3}, [%4];"
                 : "=r"(r[0]), "=r"(r[1]), "=r"(r[2]), "=r"(r[3]) : "r"(addr));
}
__device__ __forceinline__ void mma16816h(float* c, const uint32_t* a, uint32_t b0, uint32_t b1) {
    asm volatile(
        "mma.sync.aligned.m16n8k16.row.col.f32.f16.f16.f32 "
        "{%0,%1,%2,%3}, {%4,%5,%6,%7}, {%8,%9}, {%0,%1,%2,%3};"
        : "+f"(c[0]), "+f"(c[1]), "+f"(c[2]), "+f"(c[3])
        : "r"(a[0]), "r"(a[1]), "r"(a[2]), "r"(a[3]), "r"(b0), "r"(b1));
}
__device__ __forceinline__ uint32_t pack_h16(float x, float y) {
    __half2 t = __floats2half2_rn(x, y);
    return *(uint32_t*)&t;
}

// ---------------- fp16 GEMM; B fp16 [K,N] via cp.async OR fp32 [K,N] via LDG+CVT
static constexpr uint32_t TA_BYTES = 128 * 80;
static constexpr int BSTR = 264;
static constexpr uint32_t TB_BYTES = 32 * BSTR * 2;
static constexpr uint32_t TSTAGE = TA_BYTES + TB_BYTES;
static constexpr uint32_t TN_SMEM = 4 * TSTAGE;   // 108544

template <bool RELU, bool HALFOUT, bool BF32>
__global__ __launch_bounds__(512, 1) void gemm_tn(
    const __half* __restrict__ A, const void* __restrict__ Bv,
    const float* __restrict__ bias, void* __restrict__ Cout, int Nd, int Kd) {
    extern __shared__ char smem[];
    const uint32_t sb = smem_u32(smem);
    const int tid = threadIdx.x;
    const int wid = tid >> 5, lane = tid & 31;
    const int wm = wid & 1, wn = wid >> 1;
    const int bm = blockIdx.x * 128;
    const int bn = blockIdx.y * 256;
    const int NC = Kd >> 5;

    const __half* Bh = (const __half*)Bv;
    const float*  Bf = (const float*)Bv;

    const int arow = tid >> 2, aseg = tid & 3;
    const int brow = tid >> 4;            // 0..31 (k-row)
    const int bcol = (tid & 15) * 16;     // 16 floats per thread

    float4 breg[4];

    auto issueA = [&](int c) {
        const int k0 = c << 5;
        const uint32_t base = sb + (c & 3) * TSTAGE;
        cp16(base + arow * 80 + aseg * 16, A + (size_t)(bm + arow) * Kd + k0 + aseg * 8);
    };
    auto issueB16 = [&](int c) {
        const int k0 = c << 5;
        const uint32_t base = sb + (c & 3) * TSTAGE;
#pragma unroll
        for (int it = 0; it < 2; it++) {
            int i = tid + it * 512;
            int row = i >> 5, seg = i & 31;
            cp16(base + TA_BYTES + row * (BSTR * 2) + seg * 16,
                 Bh + (size_t)(k0 + row) * Nd + bn + seg * 8);
        }
    };
    auto ldgB = [&](int c) {
        const int k0 = c << 5;
        const float* src = Bf + (size_t)(k0 + brow) * Nd + bn + bcol;
#pragma unroll
        for (int j = 0; j < 4; j++) breg[j] = ((const float4*)src)[j];
    };
    auto stsB = [&](int stage) {
        uint32_t dst = sb + stage * TSTAGE + TA_BYTES + brow * (BSTR * 2) + bcol * 2;
        uint32_t hh[8];
#pragma unroll
        for (int j = 0; j < 4; j++) {
            hh[j * 2]     = pack_h16(breg[j].x, breg[j].y);
            hh[j * 2 + 1] = pack_h16(breg[j].z, breg[j].w);
        }
        asm volatile("st.shared.v4.b32 [%0], {%1,%2,%3,%4};"
                     :: "r"(dst), "r"(hh[0]), "r"(hh[1]), "r"(hh[2]), "r"(hh[3]));
        asm volatile("st.shared.v4.b32 [%0], {%1,%2,%3,%4};"
                     :: "r"(dst + 16), "r"(hh[4]), "r"(hh[5]), "r"(hh[6]), "r"(hh[7]));
    };

    // prologue
    if (BF32) {
        issueA(0); cp_commit();
        issueA(1); cp_commit();
        issueA(2); cp_commit();
        ldgB(0); stsB(0);
        ldgB(1); stsB(1);
        ldgB(2);
    } else {
        issueA(0); issueB16(0); cp_commit();
        issueA(1); issueB16(1); cp_commit();
        issueA(2); issueB16(2); cp_commit();
    }

    float acc[4][4][4];
#pragma unroll
    for (int i = 0; i < 4; i++)
#pragma unroll
        for (int j = 0; j < 4; j++)
#pragma unroll
            for (int r = 0; r < 4; r++) acc[i][j][r] = 0.f;

    const int a_r = lane & 15;
    const int a_c = (lane >> 4) << 3;
    const int tr_r = (lane & 7) + (((lane >> 3) & 1) << 3);
    const int tr_c = (lane >> 4) << 3;

    for (int c = 0; c < NC; c++) {
        cp_wait<2>();
        __syncthreads();
        if (BF32) {
            if (c + 2 < NC) stsB((c + 2) & 3);   // breg holds chunk c+2
            if (c + 3 < NC) { ldgB(c + 3); issueA(c + 3); }
            cp_commit();
        } else {
            if (c + 3 < NC) { issueA(c + 3); issueB16(c + 3); }
            cp_commit();
        }

        const uint32_t sA = sb + (c & 3) * TSTAGE;
        const uint32_t sB = sA + TA_BYTES;
#pragma unroll
        for (int kk = 0; kk < 2; kk++) {
            uint32_t a[4][4], b[2][4];
#pragma unroll
            for (int mt = 0; mt < 4; mt++)
                ldmat4(a[mt], sA + (uint32_t)(wm * 64 + mt * 16 + a_r) * 80
                              + (uint32_t)(kk * 16 + a_c) * 2);
#pragma unroll
            for (int g = 0; g < 2; g++)
                ldmat4t(b[g], sB + (uint32_t)(kk * 16 + tr_r) * (BSTR * 2)
                              + (uint32_t)(wn * 32 + g * 16 + tr_c) * 2);
#pragma unroll
            for (int mt = 0; mt < 4; mt++)
#pragma unroll
                for (int nt = 0; nt < 4; nt++)
                    mma16816h(acc[mt][nt], a[mt],
                              b[nt >> 1][(nt & 1) * 2], b[nt >> 1][(nt & 1) * 2 + 1]);
        }
    }

    const int g = lane >> 2, t = lane & 3;
#pragma unroll
    for (int mt = 0; mt < 4; mt++) {
#pragma unroll
        for (int nt = 0; nt < 4; nt++) {
            int row0 = bm + wm * 64 + mt * 16 + g;
            int col = bn + wn * 32 + nt * 8 + t * 2;
            float bx = bias[col], by = bias[col + 1];
            float2 v0, v1;
            v0.x = acc[mt][nt][0] + bx; v0.y = acc[mt][nt][1] + by;
            v1.x = acc[mt][nt][2] + bx; v1.y = acc[mt][nt][3] + by;
            if (RELU) {
                v0.x = fmaxf(v0.x, 0.f); v0.y = fmaxf(v0.y, 0.f);
                v1.x = fmaxf(v1.x, 0.f); v1.y = fmaxf(v1.y, 0.f);
            }
            if (HALFOUT) {
                __half* C = (__half*)Cout;
                *(__half2*)&C[(size_t)row0 * Nd + col] = __floats2half2_rn(v0.x, v0.y);
                *(__half2*)&C[(size_t)(row0 + 8) * Nd + col] = __floats2half2_rn(v1.x, v1.y);
            } else {
                float* C = (float*)Cout;
                *(float2*)&C[(size_t)row0 * Nd + col] = v0;
                *(float2*)&C[(size_t)(row0 + 8) * Nd + col] = v1;
            }
        }
    }
}

// ---------------- 3-source interleaved convert: Wq/Wk/Wv -> [K, 3D] fp16 -------
__global__ __launch_bounds__(256) void wconv3_kernel(
    const float* __restrict__ Wq, const float* __restrict__ Wk,
    const float* __restrict__ Wv, __half* __restrict__ out) {
    int i = blockIdx.x * 256 + threadIdx.x;
    const int per = cfg::D * cfg::D / 4;
    if (i >= 3 * per) return;
    int src = i / per, r = i % per;
    int krow = r >> 8, n4 = r & 255;
    const float* W = (src == 0) ? Wq : (src == 1) ? Wk : Wv;
    float4 v = ((const float4*)W)[r];
    size_t obase = (size_t)krow * cfg::D3 + src * cfg::D + n4 * 4;
    *(__half2*)&out[obase]     = __floats2half2_rn(v.x, v.y);
    *(__half2*)&out[obase + 2] = __floats2half2_rn(v.z, v.w);
}

__global__ void bcat_kernel(const float* __restrict__ bq, const float* __restrict__ bk,
                            const float* __restrict__ bv, float* __restrict__ out) {
    int i = threadIdx.x;
    const float* s = (blockIdx.x == 0) ? bq : (blockIdx.x == 1) ? bk : bv;
    out[blockIdx.x * cfg::D + i] = s[i];
}

// ---------------- embed + positional encoding -> fp16 --------------------------
__global__ void embed_kernel(const int* __restrict__ x, const float* __restrict__ emb,
                             __half* __restrict__ h16) {
    int row = blockIdx.x;
    int t = row & (cfg::T - 1);
    int tok = x[row];
    const float* e = emb + (size_t)tok * cfg::D;
    int d0 = threadIdx.x * 4;
    float4 ev = *(const float4*)&e[d0];
    const float cfac = -0.017988946039015984f;
    int i0 = d0 >> 1;
    float f0 = expf((float)i0 * cfac);
    float f1 = expf((float)(i0 + 1) * cfac);
    float a0 = (float)t * f0, a1 = (float)t * f1;
    __half2 p0 = __floats2half2_rn(ev.x + sinf(a0), ev.y + cosf(a0));
    __half2 p1 = __floats2half2_rn(ev.z + sinf(a1), ev.w + cosf(a1));
    uint2 pk = make_uint2(*(uint32_t*)&p0, *(uint32_t*)&p1);
    *(uint2*)&h16[(size_t)row * cfg::D + d0] = pk;
}

// ---------------- fp16 flash attention (64 q-rows, QKV strided) ----------------
static constexpr int FH = 72;

__global__ __launch_bounds__(128) void flash_half(
    const __half* __restrict__ qkv, __half* __restrict__ o16) {
    __shared__ __align__(16) __half sQ[64 * FH];
    __shared__ __align__(16) __half sK[2][64 * FH];
    __shared__ __align__(16) __half sV[2][64 * FH];

    const int qi = gridDim.x - 1 - blockIdx.x;
    const int h = blockIdx.y, b = blockIdx.z;
    const int tid = threadIdx.x;
    const int wid = tid >> 5, lane = tid & 31;
    const size_t rowbase = (size_t)b * cfg::T;
    const int hq = h * cfg::HD;

    const uint32_t uQ = smem_u32(sQ);
    const uint32_t uK0 = smem_u32(sK[0]), uV0 = smem_u32(sV[0]);

    const int a_r = lane & 15;
    const int a_c = (lane >> 4) << 3;
    const int b_r = (lane & 7) + ((lane >> 4) << 3);
    const int b_c = ((lane >> 3) & 1) << 3;
    const int kv_r = (lane & 7) + (((lane >> 3) & 1) << 3);
    const int kv_c = (lane >> 4) << 3;
    const int g = lane >> 2, t = lane & 3;

#pragma unroll
    for (int it = 0; it < 4; it++) {
        int idx = tid + it * 128;
        int r = idx >> 3, seg = idx & 7;
        cp16(uQ + r * (FH * 2) + seg * 16,
             qkv + (rowbase + qi * 64 + r) * cfg::D3 + hq + seg * 8);
    }
    cp_commit();

    auto issue_kv = [&](int kt) {
        const int buf = kt & 1;
        const uint32_t uk = uK0 + buf * (64 * FH * 2);
        const uint32_t uv = uV0 + buf * (64 * FH * 2);
#pragma unroll
        for (int it = 0; it < 4; it++) {
            int idx = tid + it * 128;
            int r = idx >> 3, seg = idx & 7;
            size_t go = (rowbase + kt * 64 + r) * cfg::D3 + hq + seg * 8;
            cp16(uk + r * (FH * 2) + seg * 16, qkv + go + cfg::D);
            cp16(uv + r * (FH * 2) + seg * 16, qkv + go + 2 * cfg::D);
        }
    };

    issue_kv(0); cp_commit();

    float accO[8][4];
#pragma unroll
    for (int i = 0; i < 8; i++)
#pragma unroll
        for (int j = 0; j < 4; j++) accO[i][j] = 0.f;
    float m0 = -1e30f, m1 = -1e30f, l0 = 0.f, l1 = 0.f;

    for (int kt = 0; kt <= qi; kt++) {
        cp_wait<0>();
        __syncthreads();
        if (kt < qi) { issue_kv(kt + 1); cp_commit(); }

        const int buf = kt & 1;
        const uint32_t uk = uK0 + buf * (64 * FH * 2);
        const uint32_t uv = uV0 + buf * (64 * FH * 2);

        float sa[8][4];
#pragma unroll
        for (int i = 0; i < 8; i++)
#pragma unroll
            for (int j = 0; j < 4; j++) sa[i][j] = 0.f;
#pragma unroll
        for (int kg = 0; kg < 4; kg++) {
            uint32_t af[4];
            ldmat4(af, uQ + (uint32_t)(wid * 16 + a_r) * (FH * 2) + (kg * 16 + a_c) * 2);
#pragma unroll
            for (int gg = 0; gg < 4; gg++) {
                uint32_t bf[4];
                ldmat4(bf, uk + (uint32_t)(gg * 16 + b_r) * (FH * 2) + (kg * 16 + b_c) * 2);
                mma16816h(sa[gg * 2], af, bf[0], bf[1]);
                mma16816h(sa[gg * 2 + 1], af, bf[2], bf[3]);
            }
        }

        const bool diag = (kt == qi);
#pragma unroll
        for (int nt = 0; nt < 8; nt++) {
            int c0 = nt * 8 + t * 2;
            sa[nt][0] *= 0.125f; sa[nt][1] *= 0.125f;
            sa[nt][2] *= 0.125f; sa[nt][3] *= 0.125f;
            if (diag) {
                int r0 = wid * 16 + g, r1 = r0 + 8;
                if (c0 > r0)     sa[nt][0] = -1e30f;
                if (c0 + 1 > r0) sa[nt][1] = -1e30f;
                if (c0 > r1)     sa[nt][2] = -1e30f;
                if (c0 + 1 > r1) sa[nt][3] = -1e30f;
            }
        }

        float mt0 = -1e30f, mt1 = -1e30f;
#pragma unroll
        for (int nt = 0; nt < 8; nt++) {
            mt0 = fmaxf(mt0, fmaxf(sa[nt][0], sa[nt][1]));
            mt1 = fmaxf(mt1, fmaxf(sa[nt][2], sa[nt][3]));
        }
#pragma unroll
        for (int off = 1; off <= 2; off <<= 1) {
            mt0 = fmaxf(mt0, __shfl_xor_sync(0xffffffffu, mt0, off));
            mt1 = fmaxf(mt1, __shfl_xor_sync(0xffffffffu, mt1, off));
        }
        float mn0 = fmaxf(m0, mt0), mn1 = fmaxf(m1, mt1);
        float al0 = __expf(m0 - mn0), al1 = __expf(m1 - mn1);
        m0 = mn0; m1 = mn1;

        float rs0 = 0.f, rs1 = 0.f;
#pragma unroll
        for (int nt = 0; nt < 8; nt++) {
            sa[nt][0] = __expf(sa[nt][0] - mn0);
            sa[nt][1] = __expf(sa[nt][1] - mn0);
            sa[nt][2] = __expf(sa[nt][2] - mn1);
            sa[nt][3] = __expf(sa[nt][3] - mn1);
            rs0 += sa[nt][0] + sa[nt][1];
            rs1 += sa[nt][2] + sa[nt][3];
        }
#pragma unroll
        for (int off = 1; off <= 2; off <<= 1) {
            rs0 += __shfl_xor_sync(0xffffffffu, rs0, off);
            rs1 += __shfl_xor_sync(0xffffffffu, rs1, off);
        }
        l0 = l0 * al0 + rs0;
        l1 = l1 * al1 + rs1;
#pragma unroll
        for (int nt = 0; nt < 8; nt++) {
            accO[nt][0] *= al0; accO[nt][1] *= al0;
            accO[nt][2] *= al1; accO[nt][3] *= al1;
        }

        uint32_t pf[4][4];
#pragma unroll
        for (int kg = 0; kg < 4; kg++) {
            pf[kg][0] = pack_h16(sa[2 * kg][0],     sa[2 * kg][1]);
            pf[kg][1] = pack_h16(sa[2 * kg][2],     sa[2 * kg][3]);
            pf[kg][2] = pack_h16(sa[2 * kg + 1][0], sa[2 * kg + 1][1]);
            pf[kg][3] = pack_h16(sa[2 * kg + 1][2], sa[2 * kg + 1][3]);
        }

#pragma unroll
        for (int kg = 0; kg < 4; kg++) {
#pragma unroll
            for (int gg = 0; gg < 4; gg++) {
                uint32_t bf[4];
                ldmat4t(bf, uv + (uint32_t)(kg * 16 + kv_r) * (FH * 2) + (gg * 16 + kv_c) * 2);
                mma16816h(accO[gg * 2], pf[kg], bf[0], bf[1]);
                mma16816h(accO[gg * 2 + 1], pf[kg], bf[2], bf[3]);
            }
        }
    }

    float inv0 = 1.0f / l0, inv1 = 1.0f / l1;
    int row0 = qi * 64 + wid * 16 + g;
    const size_t headoff = rowbase * cfg::D + (size_t)h * cfg::HD;
#pragma unroll
    for (int nt = 0; nt < 8; nt++) {
        int col = nt * 8 + t * 2;
        *(__half2*)&o16[headoff + (size_t)row0 * cfg::D + col] =
            __floats2half2_rn(accO[nt][0] * inv0, accO[nt][1] * inv0);
        *(__half2*)&o16[headoff + (size_t)(row0 + 8) * cfg::D + col] =
            __floats2half2_rn(accO[nt][2] * inv1, accO[nt][3] * inv1);
    }
}

// ---------------- layernorm (unbiased std), fp32 in -> fp16 out ----------------
__inline__ __device__ float block_reduce_sum(float val) {
    __shared__ float sbuf[8];
    int lane = threadIdx.x & 31, wid = threadIdx.x >> 5;
#pragma unroll
    for (int o = 16; o; o >>= 1) val += __shfl_xor_sync(0xffffffffu, val, o);
    if (lane == 0) sbuf[wid] = val;
    __syncthreads();
    val = (threadIdx.x < 8) ? sbuf[threadIdx.x] : 0.f;
    if (wid == 0) {
#pragma unroll
        for (int o = 4; o; o >>= 1) val += __shfl_xor_sync(0xffffffffu, val, o);
        if (lane == 0) sbuf[0] = val;
    }
    __syncthreads();
    float r = sbuf[0];
    __syncthreads();
    return r;
}

__global__ void layernorm_kernel(const float* __restrict__ in, __half* __restrict__ out16,
                                 const float* __restrict__ g, const float* __restrict__ be) {
    int row = blockIdx.x;
    const float* p = in + (size_t)row * cfg::D;
    int d0 = threadIdx.x * 4;
    float4 xv = *(const float4*)&p[d0];
    float s = xv.x + xv.y + xv.z + xv.w;
    s = block_reduce_sum(s);
    float mean = s * (1.0f / cfg::D);
    float dx[4] = {xv.x - mean, xv.y - mean, xv.z - mean, xv.w - mean};
    float sq = dx[0] * dx[0] + dx[1] * dx[1] + dx[2] * dx[2] + dx[3] * dx[3];
    sq = block_reduce_sum(sq);
    float stdv = sqrtf(sq / (float)(cfg::D - 1));
    float inv = 1.0f / (stdv + cfg::EPS);
    float4 gg = *(const float4*)&g[d0];
    float4 bb = *(const float4*)&be[d0];
    __half2 p0 = __floats2half2_rn(dx[0] * inv * gg.x + bb.x, dx[1] * inv * gg.y + bb.y);
    __half2 p1 = __floats2half2_rn(dx[2] * inv * gg.z + bb.z, dx[3] * inv * gg.w + bb.w);
    uint2 pk = make_uint2(*(uint32_t*)&p0, *(uint32_t*)&p1);
    *(uint2*)&out16[(size_t)row * cfg::D + d0] = pk;
}

// ---------------- row softmax over V=32000 (fp32 in-place) ----------------------
__global__ void softmax_kernel(float* __restrict__ out) {
    int row = blockIdx.x;
    float* p = out + (size_t)row * cfg::V;
    float m = -1e30f, s = 0.f;
    for (int j = threadIdx.x; j < cfg::V; j += 256) {
        float xv = p[j];
        if (xv > m) { s = s * __expf(m - xv) + 1.0f; m = xv; }
        else        { s += __expf(xv - m); }
    }
    __shared__ float sm[256], ss[256];
    sm[threadIdx.x] = m; ss[threadIdx.x] = s;
    __syncthreads();
    for (int off = 128; off; off >>= 1) {
        if (threadIdx.x < off) {
            float m1 = sm[threadIdx.x], s1 = ss[threadIdx.x];
            float m2 = sm[threadIdx.x + off], s2 = ss[threadIdx.x + off];
            float mm = fmaxf(m1, m2);
            sm[threadIdx.x] = mm;
            ss[threadIdx.x] = s1 * __expf(m1 - mm) + s2 * __expf(m2 - mm);
        }
        __syncthreads();
    }
    float mall = sm[0];
    float inv = 1.0f / ss[0];
    for (int j = threadIdx.x; j < cfg::V; j += 256) {
        p[j] = __expf(p[j] - mall) * inv;
    }
}

// ---------------- host orchestration -------------------------------------------
extern "C" void kernel_launch(void* const* d_in, const int* in_sizes, int n_in,
                              void* d_out, int out_size) {
    using namespace cfg;
    const int*   x   = (const int*)d_in[0];
    const float* emb = (const float*)d_in[1];
    const float* Wq  = (const float*)d_in[2];
    const float* bq  = (const float*)d_in[3];
    const float* Wk  = (const float*)d_in[4];
    const float* bk  = (const float*)d_in[5];
    const float* Wv  = (const float*)d_in[6];
    const float* bv  = (const float*)d_in[7];
    const float* Wo  = (const float*)d_in[8];
    const float* bo  = (const float*)d_in[9];
    const float* g1  = (const float*)d_in[10];
    const float* be1 = (const float*)d_in[11];
    const float* W1  = (const float*)d_in[12];
    const float* bf1 = (const float*)d_in[13];
    const float* W2  = (const float*)d_in[14];
    const float* bf2 = (const float*)d_in[15];
    const float* g2  = (const float*)d_in[16];
    const float* be2 = (const float*)d_in[17];
    const float* Wl  = (const float*)d_in[18];
    const float* bl  = (const float*)d_in[19];
    float* out = (float*)d_out;

    float *h, *o, *bqkv;
    cudaGetSymbolAddress((void**)&h, g_h);
    cudaGetSymbolAddress((void**)&o, g_o);
    cudaGetSymbolAddress((void**)&bqkv, g_bqkv);

    __half *x16, *h16, *o16, *qkv, *wqkv;
    cudaGetSymbolAddress((void**)&x16, g_x16);
    cudaGetSymbolAddress((void**)&h16, g_h16);
    cudaGetSymbolAddress((void**)&o16, g_o16);
    cudaGetSymbolAddress((void**)&qkv, g_qkv);
    cudaGetSymbolAddress((void**)&wqkv, g_wqkv);

    cudaFuncSetAttribute((const void*)gemm_tn<false, true, false>,
                         cudaFuncAttributeMaxDynamicSharedMemorySize, TN_SMEM);
    cudaFuncSetAttribute((const void*)gemm_tn<false, false, true>,
                         cudaFuncAttributeMaxDynamicSharedMemorySize, TN_SMEM);
    cudaFuncSetAttribute((const void*)gemm_tn<true, true, true>,
                         cudaFuncAttributeMaxDynamicSharedMemorySize, TN_SMEM);

    embed_kernel<<<M, 256>>>(x, emb, h16);
    wconv3_kernel<<<(3 * D * D / 4 + 255) / 256, 256>>>(Wq, Wk, Wv, wqkv);
    bcat_kernel<<<3, 1024>>>(bq, bk, bv, bqkv);

    gemm_tn<false, true, false><<<dim3(M / 128, D3 / 256), 512, TN_SMEM>>>(
        h16, wqkv, bqkv, qkv, D3, D);

    flash_half<<<dim3(T / 64, H, B), 128>>>(qkv, o16);

    gemm_tn<false, false, true><<<dim3(M / 128, D / 256), 512, TN_SMEM>>>(
        o16, Wo, bo, h, D, D);
    layernorm_kernel<<<M, 256>>>(h, h16, g1, be1);

    gemm_tn<true, true, true><<<dim3(M / 128, F / 256), 512, TN_SMEM>>>(
        h16, W1, bf1, x16, F, D);

    gemm_tn<false, false, true><<<dim3(M / 128, D / 256), 512, TN_SMEM>>>(
        x16, W2, bf2, o, D, F);
    layernorm_kernel<<<M, 256>>>(o, o16, g2, be2);

    gemm_tn<false, false, true><<<dim3(M / 128, V / 256), 512, TN_SMEM>>>(
        o16, Wl, bl, out, V, D);

    softmax_kernel<<<M, 256>>>(out);
}

// round 17
// speedup vs baseline: 1.2243x; 1.2243x over previous
#include <cuda_runtime.h>
#include <cuda_fp16.h>
#include <math.h>
#include <stdint.h>

// ---------------- problem constants ----------------
namespace cfg {
constexpr int B = 2, T = 2048, D = 1024, H = 16, HD = 64, F = 4096, V = 32000;
constexpr int M = B * T;
constexpr int D3 = 3 * D;
constexpr float EPS = 1e-6f;
}

// ---------------- scratch ----------------------------------------------------
__device__ float g_h[cfg::M * cfg::D];
__device__ float g_o[cfg::M * cfg::D];

__device__ __half g_x16[(size_t)cfg::M * cfg::F];
__device__ __half g_h16[cfg::M * cfg::D];
__device__ __half g_o16[cfg::M * cfg::D];
__device__ __half g_qkv[(size_t)cfg::M * cfg::D3];

__device__ __half g_wqkv[(size_t)cfg::D * cfg::D3];
__device__ float  g_bqkv[cfg::D3];
__device__ __half g_wo[cfg::D * cfg::D];
__device__ __half g_w1[(size_t)cfg::D * cfg::F], g_w2[(size_t)cfg::D * cfg::F];
__device__ __half g_wl[(size_t)cfg::V * cfg::D];

// ---------------- PTX helpers -------------------------------------------------
__device__ __forceinline__ uint32_t smem_u32(const void* p) {
    uint32_t a;
    asm("{ .reg .u64 t; cvta.to.shared.u64 t, %1; cvt.u32.u64 %0, t; }" : "=r"(a) : "l"(p));
    return a;
}
__device__ __forceinline__ void cp16(uint32_t dst, const void* src) {
    asm volatile("cp.async.cg.shared.global [%0], [%1], 16;" :: "r"(dst), "l"(src));
}
__device__ __forceinline__ void cp_commit() {
    asm volatile("cp.async.commit_group;" ::: "memory");
}
template <int N>
__device__ __forceinline__ void cp_wait() {
    asm volatile("cp.async.wait_group %0;" :: "n"(N) : "memory");
}
__device__ __forceinline__ void ldmat4(uint32_t* r, uint32_t addr) {
    asm volatile("ldmatrix.sync.aligned.m8n8.x4.shared.b16 {%0,%1,%2,%3}, [%4];"
                 : "=r"(r[0]), "=r"(r[1]), "=r"(r[2]), "=r"(r[3]) : "r"(addr));
}
__device__ __forceinline__ void ldmat4t(uint32_t* r, uint32_t addr) {
    asm volatile("ldmatrix.sync.aligned.m8n8.x4.trans.shared.b16 {%0,%1,%2,%3}, [%4];"
                 : "=r"(r[0]), "=r"(r[1]), "=r"(r[2]), "=r"(r[3]) : "r"(addr));
}
__device__ __forceinline__ void mma16816h(float* c, const uint32_t* a, uint32_t b0, uint32_t b1) {
    asm volatile(
        "mma.sync.aligned.m16n8k16.row.col.f32.f16.f16.f32 "
        "{%0,%1,%2,%3}, {%4,%5,%6,%7}, {%8,%9}, {%0,%1,%2,%3};"
        : "+f"(c[0]), "+f"(c[1]), "+f"(c[2]), "+f"(c[3])
        : "r"(a[0]), "r"(a[1]), "r"(a[2]), "r"(a[3]), "r"(b0), "r"(b1));
}
__device__ __forceinline__ uint32_t pack_h16(float x, float y) {
    __half2 t = __floats2half2_rn(x, y);
    return *(uint32_t*)&t;
}

// ---------------- fp16 GEMM, B in natural [K,N] layout (trans-ldmatrix) --------
static constexpr uint32_t TA_BYTES = 128 * 80;
static constexpr int BSTR = 264;
static constexpr uint32_t TB_BYTES = 32 * BSTR * 2;
static constexpr uint32_t TSTAGE = TA_BYTES + TB_BYTES;
static constexpr uint32_t TN_SMEM = 4 * TSTAGE;   // 108544

template <bool RELU, bool HALFOUT>
__global__ __launch_bounds__(512, 1) void gemm_tn(
    const __half* __restrict__ A, const __half* __restrict__ B,
    const float* __restrict__ bias, void* __restrict__ Cout, int Nd, int Kd) {
    extern __shared__ char smem[];
    const uint32_t sb = smem_u32(smem);
    const int tid = threadIdx.x;
    const int wid = tid >> 5, lane = tid & 31;
    const int wm = wid & 1, wn = wid >> 1;
    const int bm = blockIdx.x * 128;
    const int bn = blockIdx.y * 256;
    const int NC = Kd >> 5;

    const int arow = tid >> 2, aseg = tid & 3;

    auto issue = [&](int c) {
        const int k0 = c << 5;
        const uint32_t base = sb + (c & 3) * TSTAGE;
        cp16(base + arow * 80 + aseg * 16, A + (size_t)(bm + arow) * Kd + k0 + aseg * 8);
#pragma unroll
        for (int it = 0; it < 2; it++) {
            int i = tid + it * 512;
            int row = i >> 5, seg = i & 31;
            cp16(base + TA_BYTES + row * (BSTR * 2) + seg * 16,
                 B + (size_t)(k0 + row) * Nd + bn + seg * 8);
        }
    };

    issue(0); cp_commit();
    issue(1); cp_commit();
    issue(2); cp_commit();

    float acc[4][4][4];
#pragma unroll
    for (int i = 0; i < 4; i++)
#pragma unroll
        for (int j = 0; j < 4; j++)
#pragma unroll
            for (int r = 0; r < 4; r++) acc[i][j][r] = 0.f;

    const int a_r = lane & 15;
    const int a_c = (lane >> 4) << 3;
    const int tr_r = (lane & 7) + (((lane >> 3) & 1) << 3);
    const int tr_c = (lane >> 4) << 3;

    for (int c = 0; c < NC; c++) {
        cp_wait<2>();
        __syncthreads();
        if (c + 3 < NC) issue(c + 3);
        cp_commit();

        const uint32_t sA = sb + (c & 3) * TSTAGE;
        const uint32_t sB = sA + TA_BYTES;
#pragma unroll
        for (int kk = 0; kk < 2; kk++) {
            uint32_t a[4][4], b[2][4];
#pragma unroll
            for (int mt = 0; mt < 4; mt++)
                ldmat4(a[mt], sA + (uint32_t)(wm * 64 + mt * 16 + a_r) * 80
                              + (uint32_t)(kk * 16 + a_c) * 2);
#pragma unroll
            for (int g = 0; g < 2; g++)
                ldmat4t(b[g], sB + (uint32_t)(kk * 16 + tr_r) * (BSTR * 2)
                              + (uint32_t)(wn * 32 + g * 16 + tr_c) * 2);
#pragma unroll
            for (int mt = 0; mt < 4; mt++)
#pragma unroll
                for (int nt = 0; nt < 4; nt++)
                    mma16816h(acc[mt][nt], a[mt],
                              b[nt >> 1][(nt & 1) * 2], b[nt >> 1][(nt & 1) * 2 + 1]);
        }
    }

    const int g = lane >> 2, t = lane & 3;
#pragma unroll
    for (int mt = 0; mt < 4; mt++) {
#pragma unroll
        for (int nt = 0; nt < 4; nt++) {
            int row0 = bm + wm * 64 + mt * 16 + g;
            int col = bn + wn * 32 + nt * 8 + t * 2;
            float bx = bias[col], by = bias[col + 1];
            float2 v0, v1;
            v0.x = acc[mt][nt][0] + bx; v0.y = acc[mt][nt][1] + by;
            v1.x = acc[mt][nt][2] + bx; v1.y = acc[mt][nt][3] + by;
            if (RELU) {
                v0.x = fmaxf(v0.x, 0.f); v0.y = fmaxf(v0.y, 0.f);
                v1.x = fmaxf(v1.x, 0.f); v1.y = fmaxf(v1.y, 0.f);
            }
            if (HALFOUT) {
                __half* C = (__half*)Cout;
                *(__half2*)&C[(size_t)row0 * Nd + col] = __floats2half2_rn(v0.x, v0.y);
                *(__half2*)&C[(size_t)(row0 + 8) * Nd + col] = __floats2half2_rn(v1.x, v1.y);
            } else {
                float* C = (float*)Cout;
                *(float2*)&C[(size_t)row0 * Nd + col] = v0;
                *(float2*)&C[(size_t)(row0 + 8) * Nd + col] = v1;
            }
        }
    }
}

// ---------------- weight convert fp32 -> fp16 -----------------------------------
__global__ __launch_bounds__(256) void wconv_kernel(
    const float* __restrict__ W, __half* __restrict__ out, int n4) {
    const int stride = gridDim.x * 256;
    int i = blockIdx.x * 256 + threadIdx.x;
    for (; i + 3 * stride < n4; i += 4 * stride) {
        float4 v0 = ((const float4*)W)[i];
        float4 v1 = ((const float4*)W)[i + stride];
        float4 v2 = ((const float4*)W)[i + 2 * stride];
        float4 v3 = ((const float4*)W)[i + 3 * stride];
        ((__half2*)out)[(size_t)i * 2]                    = __floats2half2_rn(v0.x, v0.y);
        ((__half2*)out)[(size_t)i * 2 + 1]                = __floats2half2_rn(v0.z, v0.w);
        ((__half2*)out)[((size_t)i + stride) * 2]         = __floats2half2_rn(v1.x, v1.y);
        ((__half2*)out)[((size_t)i + stride) * 2 + 1]     = __floats2half2_rn(v1.z, v1.w);
        ((__half2*)out)[((size_t)i + 2 * stride) * 2]     = __floats2half2_rn(v2.x, v2.y);
        ((__half2*)out)[((size_t)i + 2 * stride) * 2 + 1] = __floats2half2_rn(v2.z, v2.w);
        ((__half2*)out)[((size_t)i + 3 * stride) * 2]     = __floats2half2_rn(v3.x, v3.y);
        ((__half2*)out)[((size_t)i + 3 * stride) * 2 + 1] = __floats2half2_rn(v3.z, v3.w);
    }
    for (; i < n4; i += stride) {
        float4 v = ((const float4*)W)[i];
        ((__half2*)out)[(size_t)i * 2]     = __floats2half2_rn(v.x, v.y);
        ((__half2*)out)[(size_t)i * 2 + 1] = __floats2half2_rn(v.z, v.w);
    }
}

// ---------------- 3-source interleaved convert: Wq/Wk/Wv -> [K, 3D] fp16 -------
__global__ __launch_bounds__(256) void wconv3_kernel(
    const float* __restrict__ Wq, const float* __restrict__ Wk,
    const float* __restrict__ Wv, __half* __restrict__ out) {
    int i = blockIdx.x * 256 + threadIdx.x;
    const int per = cfg::D * cfg::D / 4;
    if (i >= 3 * per) return;
    int src = i / per, r = i % per;
    int krow = r >> 8, n4 = r & 255;
    const float* W = (src == 0) ? Wq : (src == 1) ? Wk : Wv;
    float4 v = ((const float4*)W)[r];
    size_t obase = (size_t)krow * cfg::D3 + src * cfg::D + n4 * 4;
    *(__half2*)&out[obase]     = __floats2half2_rn(v.x, v.y);
    *(__half2*)&out[obase + 2] = __floats2half2_rn(v.z, v.w);
}

__global__ void bcat_kernel(const float* __restrict__ bq, const float* __restrict__ bk,
                            const float* __restrict__ bv, float* __restrict__ out) {
    int i = threadIdx.x;
    const float* s = (blockIdx.x == 0) ? bq : (blockIdx.x == 1) ? bk : bv;
    out[blockIdx.x * cfg::D + i] = s[i];
}

// ---------------- embed + positional encoding -> fp16 --------------------------
__global__ void embed_kernel(const int* __restrict__ x, const float* __restrict__ emb,
                             __half* __restrict__ h16) {
    int row = blockIdx.x;
    int t = row & (cfg::T - 1);
    int tok = x[row];
    const float* e = emb + (size_t)tok * cfg::D;
    int d0 = threadIdx.x * 4;
    float4 ev = *(const float4*)&e[d0];
    const float cfac = -0.017988946039015984f;
    int i0 = d0 >> 1;
    float f0 = expf((float)i0 * cfac);
    float f1 = expf((float)(i0 + 1) * cfac);
    float a0 = (float)t * f0, a1 = (float)t * f1;
    __half2 p0 = __floats2half2_rn(ev.x + sinf(a0), ev.y + cosf(a0));
    __half2 p1 = __floats2half2_rn(ev.z + sinf(a1), ev.w + cosf(a1));
    uint2 pk = make_uint2(*(uint32_t*)&p0, *(uint32_t*)&p1);
    *(uint2*)&h16[(size_t)row * cfg::D + d0] = pk;
}

// ---------------- fp16 flash attention (64 q-rows, QKV strided) ----------------
static constexpr int FH = 72;

__global__ __launch_bounds__(128) void flash_half(
    const __half* __restrict__ qkv, __half* __restrict__ o16) {
    __shared__ __align__(16) __half sQ[64 * FH];
    __shared__ __align__(16) __half sK[2][64 * FH];
    __shared__ __align__(16) __half sV[2][64 * FH];

    const int qi = gridDim.x - 1 - blockIdx.x;
    const int h = blockIdx.y, b = blockIdx.z;
    const int tid = threadIdx.x;
    const int wid = tid >> 5, lane = tid & 31;
    const size_t rowbase = (size_t)b * cfg::T;
    const int hq = h * cfg::HD;

    const uint32_t uQ = smem_u32(sQ);
    const uint32_t uK0 = smem_u32(sK[0]), uV0 = smem_u32(sV[0]);

    const int a_r = lane & 15;
    const int a_c = (lane >> 4) << 3;
    const int b_r = (lane & 7) + ((lane >> 4) << 3);
    const int b_c = ((lane >> 3) & 1) << 3;
    const int kv_r = (lane & 7) + (((lane >> 3) & 1) << 3);
    const int kv_c = (lane >> 4) << 3;
    const int g = lane >> 2, t = lane & 3;

#pragma unroll
    for (int it = 0; it < 4; it++) {
        int idx = tid + it * 128;
        int r = idx >> 3, seg = idx & 7;
        cp16(uQ + r * (FH * 2) + seg * 16,
             qkv + (rowbase + qi * 64 + r) * cfg::D3 + hq + seg * 8);
    }
    cp_commit();

    auto issue_kv = [&](int kt) {
        const int buf = kt & 1;
        const uint32_t uk = uK0 + buf * (64 * FH * 2);
        const uint32_t uv = uV0 + buf * (64 * FH * 2);
#pragma unroll
        for (int it = 0; it < 4; it++) {
            int idx = tid + it * 128;
            int r = idx >> 3, seg = idx & 7;
            size_t go = (rowbase + kt * 64 + r) * cfg::D3 + hq + seg * 8;
            cp16(uk + r * (FH * 2) + seg * 16, qkv + go + cfg::D);
            cp16(uv + r * (FH * 2) + seg * 16, qkv + go + 2 * cfg::D);
        }
    };

    issue_kv(0); cp_commit();

    float accO[8][4];
#pragma unroll
    for (int i = 0; i < 8; i++)
#pragma unroll
        for (int j = 0; j < 4; j++) accO[i][j] = 0.f;
    float m0 = -1e30f, m1 = -1e30f, l0 = 0.f, l1 = 0.f;

    for (int kt = 0; kt <= qi; kt++) {
        cp_wait<0>();
        __syncthreads();
        if (kt < qi) { issue_kv(kt + 1); cp_commit(); }

        const int buf = kt & 1;
        const uint32_t uk = uK0 + buf * (64 * FH * 2);
        const uint32_t uv = uV0 + buf * (64 * FH * 2);

        float sa[8][4];
#pragma unroll
        for (int i = 0; i < 8; i++)
#pragma unroll
            for (int j = 0; j < 4; j++) sa[i][j] = 0.f;
#pragma unroll
        for (int kg = 0; kg < 4; kg++) {
            uint32_t af[4];
            ldmat4(af, uQ + (uint32_t)(wid * 16 + a_r) * (FH * 2) + (kg * 16 + a_c) * 2);
#pragma unroll
            for (int gg = 0; gg < 4; gg++) {
                uint32_t bf[4];
                ldmat4(bf, uk + (uint32_t)(gg * 16 + b_r) * (FH * 2) + (kg * 16 + b_c) * 2);
                mma16816h(sa[gg * 2], af, bf[0], bf[1]);
                mma16816h(sa[gg * 2 + 1], af, bf[2], bf[3]);
            }
        }

        const bool diag = (kt == qi);
#pragma unroll
        for (int nt = 0; nt < 8; nt++) {
            int c0 = nt * 8 + t * 2;
            sa[nt][0] *= 0.125f; sa[nt][1] *= 0.125f;
            sa[nt][2] *= 0.125f; sa[nt][3] *= 0.125f;
            if (diag) {
                int r0 = wid * 16 + g, r1 = r0 + 8;
                if (c0 > r0)     sa[nt][0] = -1e30f;
                if (c0 + 1 > r0) sa[nt][1] = -1e30f;
                if (c0 > r1)     sa[nt][2] = -1e30f;
                if (c0 + 1 > r1) sa[nt][3] = -1e30f;
            }
        }

        float mt0 = -1e30f, mt1 = -1e30f;
#pragma unroll
        for (int nt = 0; nt < 8; nt++) {
            mt0 = fmaxf(mt0, fmaxf(sa[nt][0], sa[nt][1]));
            mt1 = fmaxf(mt1, fmaxf(sa[nt][2], sa[nt][3]));
        }
#pragma unroll
        for (int off = 1; off <= 2; off <<= 1) {
            mt0 = fmaxf(mt0, __shfl_xor_sync(0xffffffffu, mt0, off));
            mt1 = fmaxf(mt1, __shfl_xor_sync(0xffffffffu, mt1, off));
        }
        float mn0 = fmaxf(m0, mt0), mn1 = fmaxf(m1, mt1);
        float al0 = __expf(m0 - mn0), al1 = __expf(m1 - mn1);
        m0 = mn0; m1 = mn1;

        float rs0 = 0.f, rs1 = 0.f;
#pragma unroll
        for (int nt = 0; nt < 8; nt++) {
            sa[nt][0] = __expf(sa[nt][0] - mn0);
            sa[nt][1] = __expf(sa[nt][1] - mn0);
            sa[nt][2] = __expf(sa[nt][2] - mn1);
            sa[nt][3] = __expf(sa[nt][3] - mn1);
            rs0 += sa[nt][0] + sa[nt][1];
            rs1 += sa[nt][2] + sa[nt][3];
        }
#pragma unroll
        for (int off = 1; off <= 2; off <<= 1) {
            rs0 += __shfl_xor_sync(0xffffffffu, rs0, off);
            rs1 += __shfl_xor_sync(0xffffffffu, rs1, off);
        }
        l0 = l0 * al0 + rs0;
        l1 = l1 * al1 + rs1;
#pragma unroll
        for (int nt = 0; nt < 8; nt++) {
            accO[nt][0] *= al0; accO[nt][1] *= al0;
            accO[nt][2] *= al1; accO[nt][3] *= al1;
        }

        uint32_t pf[4][4];
#pragma unroll
        for (int kg = 0; kg < 4; kg++) {
            pf[kg][0] = pack_h16(sa[2 * kg][0],     sa[2 * kg][1]);
            pf[kg][1] = pack_h16(sa[2 * kg][2],     sa[2 * kg][3]);
            pf[kg][2] = pack_h16(sa[2 * kg + 1][0], sa[2 * kg + 1][1]);
            pf[kg][3] = pack_h16(sa[2 * kg + 1][2], sa[2 * kg + 1][3]);
        }

#pragma unroll
        for (int kg = 0; kg < 4; kg++) {
#pragma unroll
            for (int gg = 0; gg < 4; gg++) {
                uint32_t bf[4];
                ldmat4t(bf, uv + (uint32_t)(kg * 16 + kv_r) * (FH * 2) + (gg * 16 + kv_c) * 2);
                mma16816h(accO[gg * 2], pf[kg], bf[0], bf[1]);
                mma16816h(accO[gg * 2 + 1], pf[kg], bf[2], bf[3]);
            }
        }
    }

    float inv0 = 1.0f / l0, inv1 = 1.0f / l1;
    int row0 = qi * 64 + wid * 16 + g;
    const size_t headoff = rowbase * cfg::D + (size_t)h * cfg::HD;
#pragma unroll
    for (int nt = 0; nt < 8; nt++) {
        int col = nt * 8 + t * 2;
        *(__half2*)&o16[headoff + (size_t)row0 * cfg::D + col] =
            __floats2half2_rn(accO[nt][0] * inv0, accO[nt][1] * inv0);
        *(__half2*)&o16[headoff + (size_t)(row0 + 8) * cfg::D + col] =
            __floats2half2_rn(accO[nt][2] * inv1, accO[nt][3] * inv1);
    }
}

// ---------------- layernorm (unbiased std), fp32 in -> fp16 out ----------------
__inline__ __device__ float block_reduce_sum(float val) {
    __shared__ float sbuf[8];
    int lane = threadIdx.x & 31, wid = threadIdx.x >> 5;
#pragma unroll
    for (int o = 16; o; o >>= 1) val += __shfl_xor_sync(0xffffffffu, val, o);
    if (lane == 0) sbuf[wid] = val;
    __syncthreads();
    val = (threadIdx.x < 8) ? sbuf[threadIdx.x] : 0.f;
    if (wid == 0) {
#pragma unroll
        for (int o = 4; o; o >>= 1) val += __shfl_xor_sync(0xffffffffu, val, o);
        if (lane == 0) sbuf[0] = val;
    }
    __syncthreads();
    float r = sbuf[0];
    __syncthreads();
    return r;
}

__global__ void layernorm_kernel(const float* __restrict__ in, __half* __restrict__ out16,
                                 const float* __restrict__ g, const float* __restrict__ be) {
    int row = blockIdx.x;
    const float* p = in + (size_t)row * cfg::D;
    int d0 = threadIdx.x * 4;
    float4 xv = *(const float4*)&p[d0];
    float s = xv.x + xv.y + xv.z + xv.w;
    s = block_reduce_sum(s);
    float mean = s * (1.0f / cfg::D);
    float dx[4] = {xv.x - mean, xv.y - mean, xv.z - mean, xv.w - mean};
    float sq = dx[0] * dx[0] + dx[1] * dx[1] + dx[2] * dx[2] + dx[3] * dx[3];
    sq = block_reduce_sum(sq);
    float stdv = sqrtf(sq / (float)(cfg::D - 1));
    float inv = 1.0f / (stdv + cfg::EPS);
    float4 gg = *(const float4*)&g[d0];
    float4 bb = *(const float4*)&be[d0];
    __half2 p0 = __floats2half2_rn(dx[0] * inv * gg.x + bb.x, dx[1] * inv * gg.y + bb.y);
    __half2 p1 = __floats2half2_rn(dx[2] * inv * gg.z + bb.z, dx[3] * inv * gg.w + bb.w);
    uint2 pk = make_uint2(*(uint32_t*)&p0, *(uint32_t*)&p1);
    *(uint2*)&out16[(size_t)row * cfg::D + d0] = pk;
}

// ---------------- row softmax over V=32000 (fp32 in-place, float4, 512 thr) ----
__global__ __launch_bounds__(512) void softmax_kernel(float* __restrict__ out) {
    int row = blockIdx.x;
    float4* p4 = (float4*)(out + (size_t)row * cfg::V);
    const int N4 = cfg::V / 4;   // 8000
    float m = -1e30f, s = 0.f;
    for (int j = threadIdx.x; j < N4; j += 512) {
        float4 v = p4[j];
        float mx = fmaxf(fmaxf(v.x, v.y), fmaxf(v.z, v.w));
        if (mx > m) {
            s = s * __expf(m - mx) + __expf(v.x - mx) + __expf(v.y - mx)
              + __expf(v.z - mx) + __expf(v.w - mx);
            m = mx;
        } else {
            s += __expf(v.x - m) + __expf(v.y - m) + __expf(v.z - m) + __expf(v.w - m);
        }
    }
    __shared__ float sm[512], ss[512];
    sm[threadIdx.x] = m; ss[threadIdx.x] = s;
    __syncthreads();
    for (int off = 256; off; off >>= 1) {
        if (threadIdx.x < off) {
            float m1 = sm[threadIdx.x], s1 = ss[threadIdx.x];
            float m2 = sm[threadIdx.x + off], s2 = ss[threadIdx.x + off];
            float mm = fmaxf(m1, m2);
            sm[threadIdx.x] = mm;
            ss[threadIdx.x] = s1 * __expf(m1 - mm) + s2 * __expf(m2 - mm);
        }
        __syncthreads();
    }
    float mall = sm[0];
    float inv = 1.0f / ss[0];
    for (int j = threadIdx.x; j < N4; j += 512) {
        float4 v = p4[j];
        v.x = __expf(v.x - mall) * inv;
        v.y = __expf(v.y - mall) * inv;
        v.z = __expf(v.z - mall) * inv;
        v.w = __expf(v.w - mall) * inv;
        p4[j] = v;
    }
}

// ---------------- host orchestration -------------------------------------------
extern "C" void kernel_launch(void* const* d_in, const int* in_sizes, int n_in,
                              void* d_out, int out_size) {
    using namespace cfg;
    const int*   x   = (const int*)d_in[0];
    const float* emb = (const float*)d_in[1];
    const float* Wq  = (const float*)d_in[2];
    const float* bq  = (const float*)d_in[3];
    const float* Wk  = (const float*)d_in[4];
    const float* bk  = (const float*)d_in[5];
    const float* Wv  = (const float*)d_in[6];
    const float* bv  = (const float*)d_in[7];
    const float* Wo  = (const float*)d_in[8];
    const float* bo  = (const float*)d_in[9];
    const float* g1  = (const float*)d_in[10];
    const float* be1 = (const float*)d_in[11];
    const float* W1  = (const float*)d_in[12];
    const float* bf1 = (const float*)d_in[13];
    const float* W2  = (const float*)d_in[14];
    const float* bf2 = (const float*)d_in[15];
    const float* g2  = (const float*)d_in[16];
    const float* be2 = (const float*)d_in[17];
    const float* Wl  = (const float*)d_in[18];
    const float* bl  = (const float*)d_in[19];
    float* out = (float*)d_out;

    float *h, *o, *bqkv;
    cudaGetSymbolAddress((void**)&h, g_h);
    cudaGetSymbolAddress((void**)&o, g_o);
    cudaGetSymbolAddress((void**)&bqkv, g_bqkv);

    __half *x16, *h16, *o16, *qkv, *wqkv, *wo, *w1, *w2, *wl;
    cudaGetSymbolAddress((void**)&x16, g_x16);
    cudaGetSymbolAddress((void**)&h16, g_h16);
    cudaGetSymbolAddress((void**)&o16, g_o16);
    cudaGetSymbolAddress((void**)&qkv, g_qkv);
    cudaGetSymbolAddress((void**)&wqkv, g_wqkv);
    cudaGetSymbolAddress((void**)&wo, g_wo);
    cudaGetSymbolAddress((void**)&w1, g_w1);
    cudaGetSymbolAddress((void**)&w2, g_w2);
    cudaGetSymbolAddress((void**)&wl, g_wl);

    cudaFuncSetAttribute((const void*)gemm_tn<false, false>,
                         cudaFuncAttributeMaxDynamicSharedMemorySize, TN_SMEM);
    cudaFuncSetAttribute((const void*)gemm_tn<true, true>,
                         cudaFuncAttributeMaxDynamicSharedMemorySize, TN_SMEM);
    cudaFuncSetAttribute((const void*)gemm_tn<false, true>,
                         cudaFuncAttributeMaxDynamicSharedMemorySize, TN_SMEM);

    const int WG = 1184;
    embed_kernel<<<M, 256>>>(x, emb, h16);
    wconv3_kernel<<<(3 * D * D / 4 + 255) / 256, 256>>>(Wq, Wk, Wv, wqkv);
    bcat_kernel<<<3, 1024>>>(bq, bk, bv, bqkv);
    wconv_kernel<<<WG, 256>>>(Wo, wo, D * D / 4);

    gemm_tn<false, true><<<dim3(M / 128, D3 / 256), 512, TN_SMEM>>>(h16, wqkv, bqkv, qkv, D3, D);

    flash_half<<<dim3(T / 64, H, B), 128>>>(qkv, o16);

    gemm_tn<false, false><<<dim3(M / 128, D / 256), 512, TN_SMEM>>>(o16, wo, bo, h, D, D);
    layernorm_kernel<<<M, 256>>>(h, h16, g1, be1);

    wconv_kernel<<<WG, 256>>>(W1, w1, D * F / 4);
    gemm_tn<true, true><<<dim3(M / 128, F / 256), 512, TN_SMEM>>>(h16, w1, bf1, x16, F, D);

    wconv_kernel<<<WG, 256>>>(W2, w2, D * F / 4);
    gemm_tn<false, false><<<dim3(M / 128, D / 256), 512, TN_SMEM>>>(x16, w2, bf2, o, D, F);
    layernorm_kernel<<<M, 256>>>(o, o16, g2, be2);

    wconv_kernel<<<WG, 256>>>(Wl, wl, (int)((size_t)D * V / 4));
    gemm_tn<false, false><<<dim3(M / 128, V / 256), 512, TN_SMEM>>>(o16, wl, bl, out, V, D);

    softmax_kernel<<<M, 512>>>(out);
}